// round 2
// baseline (speedup 1.0000x reference)
#include <cuda_runtime.h>
#include <cstdint>

// Problem constants (fixed by setup_inputs)
#define N_NODES 8192
#define IN_DIM  256
#define OUT_DIM 64
#define SLOPE   0.2f

// Scratch (allocation-free rule: __device__ globals)
__device__ float g_proj[N_NODES * OUT_DIM];   // 2 MB
__device__ float g_si[N_NODES];
__device__ float g_sj[N_NODES];

// ---------------------------------------------------------------------------
// Kernel 1: proj = X[8192,256] @ W[256,64]   (fp32 SIMT tiled GEMM)
// ---------------------------------------------------------------------------
#define GM_BM 128
#define GM_BK 32
#define AS_LD 132

__global__ __launch_bounds__(256) void gemm_proj_kernel(
    const float* __restrict__ X, const float* __restrict__ W)
{
    __shared__ float As[GM_BK * AS_LD];     // [k][m], padded
    __shared__ float Bs[GM_BK][OUT_DIM];    // [k][n]

    const int tid = threadIdx.x;
    const int block_row = blockIdx.x * GM_BM;
    const int trow = tid / 16;   // 0..15, 8 rows each
    const int tcol = tid % 16;   // 0..15, 4 cols each

    float acc[8][4];
    #pragma unroll
    for (int i = 0; i < 8; i++)
        #pragma unroll
        for (int j = 0; j < 4; j++) acc[i][j] = 0.0f;

    for (int k0 = 0; k0 < IN_DIM; k0 += GM_BK) {
        #pragma unroll
        for (int i = 0; i < 4; i++) {
            int idx = tid + i * 256;
            int r   = idx >> 3;
            int c4  = idx & 7;
            float4 v = *(const float4*)(X + (size_t)(block_row + r) * IN_DIM + k0 + c4 * 4);
            As[(c4 * 4 + 0) * AS_LD + r] = v.x;
            As[(c4 * 4 + 1) * AS_LD + r] = v.y;
            As[(c4 * 4 + 2) * AS_LD + r] = v.z;
            As[(c4 * 4 + 3) * AS_LD + r] = v.w;
        }
        #pragma unroll
        for (int i = 0; i < 2; i++) {
            int idx = tid + i * 256;
            int r   = idx >> 4;
            int c4  = idx & 15;
            float4 v = *(const float4*)(W + (size_t)(k0 + r) * OUT_DIM + c4 * 4);
            *(float4*)&Bs[r][c4 * 4] = v;
        }
        __syncthreads();

        #pragma unroll
        for (int k = 0; k < GM_BK; k++) {
            float a[8], b[4];
            #pragma unroll
            for (int i = 0; i < 8; i++) a[i] = As[k * AS_LD + trow * 8 + i];
            #pragma unroll
            for (int j = 0; j < 4; j++) b[j] = Bs[k][tcol * 4 + j];
            #pragma unroll
            for (int i = 0; i < 8; i++)
                #pragma unroll
                for (int j = 0; j < 4; j++)
                    acc[i][j] = fmaf(a[i], b[j], acc[i][j]);
        }
        __syncthreads();
    }

    #pragma unroll
    for (int i = 0; i < 8; i++) {
        int row = block_row + trow * 8 + i;
        float4 v = make_float4(acc[i][0], acc[i][1], acc[i][2], acc[i][3]);
        *(float4*)(g_proj + (size_t)row * OUT_DIM + tcol * 4) = v;
    }
}

// ---------------------------------------------------------------------------
// Kernel 2: s_i[n] = proj[n] . a[0:64],  s_j[n] = proj[n] . a[64:128]
// ---------------------------------------------------------------------------
__global__ __launch_bounds__(256) void compute_s_kernel(const float* __restrict__ a)
{
    int row  = blockIdx.x * 8 + (threadIdx.x >> 5);
    int lane = threadIdx.x & 31;
    if (row >= N_NODES) return;

    float v0 = g_proj[(size_t)row * OUT_DIM + lane];
    float v1 = g_proj[(size_t)row * OUT_DIM + 32 + lane];
    float p0 = v0 * a[lane]      + v1 * a[32 + lane];
    float p1 = v0 * a[64 + lane] + v1 * a[96 + lane];
    #pragma unroll
    for (int o = 16; o > 0; o >>= 1) {
        p0 += __shfl_xor_sync(0xffffffffu, p0, o);
        p1 += __shfl_xor_sync(0xffffffffu, p1, o);
    }
    if (lane == 0) { g_si[row] = p0; g_sj[row] = p1; }
}

// ---------------------------------------------------------------------------
// Kernel 3: per-row sparse softmax-attention.
// adjacency is read as 32-bit words (handles both int32 0/1 and float32
// 0.0/1.0 encodings of the original bool matrix): nonzero word == edge.
// Deterministic neighbor-list build: count + block exclusive scan + ordered
// write (no atomics -> fixed fp summation order every launch).
// ---------------------------------------------------------------------------
#define CAP 1024

__device__ __forceinline__ float leaky(float x) {
    return x > 0.0f ? x : SLOPE * x;
}

__device__ __forceinline__ float block_reduce(float v, float* s8, bool do_max)
{
    int lane = threadIdx.x & 31;
    int warp = threadIdx.x >> 5;
    #pragma unroll
    for (int o = 16; o > 0; o >>= 1) {
        float t = __shfl_xor_sync(0xffffffffu, v, o);
        v = do_max ? fmaxf(v, t) : (v + t);
    }
    __syncthreads();
    if (lane == 0) s8[warp] = v;
    __syncthreads();
    if (threadIdx.x == 0) {
        float r = s8[0];
        #pragma unroll
        for (int w = 1; w < 8; w++)
            r = do_max ? fmaxf(r, s8[w]) : (r + s8[w]);
        s8[0] = r;
    }
    __syncthreads();
    return s8[0];
}

__global__ __launch_bounds__(256) void attn_kernel(
    const unsigned* __restrict__ adj, float* __restrict__ out)
{
    __shared__ int   s_idx[CAP];
    __shared__ float s_w[CAP];
    __shared__ float s_acc[4][OUT_DIM];
    __shared__ float s_red[8];
    __shared__ int   s_wsum[8];
    __shared__ int   s_woff[8];
    __shared__ int   s_cnt;

    const int row = blockIdx.x;
    const int tid = threadIdx.x;
    const int lane = tid & 31;
    const int warp = tid >> 5;

    const unsigned* arow = adj + (size_t)row * N_NODES;   // 8192 words = 32 KB
    const uint4* arow4 = (const uint4*)arow;

    // ---- pass 1: count edges per thread (8 uint4 = 32 elements each) ----
    int c = 0;
    #pragma unroll
    for (int it = 0; it < 8; it++) {
        uint4 v = arow4[tid + it * 256];
        c += (v.x != 0u) + (v.y != 0u) + (v.z != 0u) + (v.w != 0u);
    }

    // ---- block exclusive scan over per-thread counts ----
    int inc = c;
    #pragma unroll
    for (int o = 1; o < 32; o <<= 1) {
        int t = __shfl_up_sync(0xffffffffu, inc, o);
        if (lane >= o) inc += t;
    }
    if (lane == 31) s_wsum[warp] = inc;
    __syncthreads();
    if (tid == 0) {
        int s = 0;
        #pragma unroll
        for (int w = 0; w < 8; w++) { s_woff[w] = s; s += s_wsum[w]; }
        s_cnt = s;
    }
    __syncthreads();
    int off = s_woff[warp] + inc - c;   // exclusive prefix for this thread
    const int cnt = s_cnt;

    // ---- pass 2: ordered write of neighbor indices (row in L1 now) ----
    if (cnt <= CAP) {
        #pragma unroll
        for (int it = 0; it < 8; it++) {
            int i4 = tid + it * 256;
            uint4 v = arow4[i4];
            int base = i4 * 4;
            if (v.x) s_idx[off++] = base + 0;
            if (v.y) s_idx[off++] = base + 1;
            if (v.z) s_idx[off++] = base + 2;
            if (v.w) s_idx[off++] = base + 3;
        }
    }
    __syncthreads();

    const float si_r = g_si[row];
    const int   g    = tid >> 6;      // group 0..3
    const int   d    = tid & 63;      // output dim

    if (cnt == 0) {
        // softmax over all-NEG_BIG row is uniform: out = mean(proj)
        float acc = 0.0f;
        for (int j = g; j < N_NODES; j += 4)
            acc += g_proj[(size_t)j * OUT_DIM + d];
        s_acc[g][d] = acc;
        __syncthreads();
        if (g == 0) {
            float tot = s_acc[0][d] + s_acc[1][d] + s_acc[2][d] + s_acc[3][d];
            out[(size_t)row * OUT_DIM + d] = tot * (1.0f / (float)N_NODES);
        }
        return;
    }

    if (cnt <= CAP) {
        // ---- fast path: list-based softmax ----
        float lm = -INFINITY;
        for (int k = tid; k < cnt; k += 256) {
            float e = leaky(si_r + g_sj[s_idx[k]]);
            s_w[k] = e;
            lm = fmaxf(lm, e);
        }
        float m = block_reduce(lm, s_red, true);

        float ls = 0.0f;
        for (int k = tid; k < cnt; k += 256) {
            float w = __expf(s_w[k] - m);
            s_w[k] = w;
            ls += w;
        }
        float denom = block_reduce(ls, s_red, false);

        float acc = 0.0f;
        for (int k = g; k < cnt; k += 4)
            acc += s_w[k] * g_proj[(size_t)s_idx[k] * OUT_DIM + d];
        s_acc[g][d] = acc;
        __syncthreads();
        if (g == 0) {
            float tot = s_acc[0][d] + s_acc[1][d] + s_acc[2][d] + s_acc[3][d];
            out[(size_t)row * OUT_DIM + d] = tot / denom;
        }
        return;
    }

    // ---- overflow fallback (cnt > CAP, not expected at p=0.01) ----
    float lm = -INFINITY;
    for (int j = tid; j < N_NODES; j += 256)
        if (arow[j]) lm = fmaxf(lm, leaky(si_r + g_sj[j]));
    float m = block_reduce(lm, s_red, true);

    float ls = 0.0f;
    for (int j = tid; j < N_NODES; j += 256)
        if (arow[j]) ls += __expf(leaky(si_r + g_sj[j]) - m);
    float denom = block_reduce(ls, s_red, false);

    float acc = 0.0f;
    for (int j = g; j < N_NODES; j += 4)
        if (arow[j]) {
            float w = __expf(leaky(si_r + g_sj[j]) - m);
            acc += w * g_proj[(size_t)j * OUT_DIM + d];
        }
    s_acc[g][d] = acc;
    __syncthreads();
    if (g == 0) {
        float tot = s_acc[0][d] + s_acc[1][d] + s_acc[2][d] + s_acc[3][d];
        out[(size_t)row * OUT_DIM + d] = tot / denom;
    }
}

// ---------------------------------------------------------------------------
// Launch
// ---------------------------------------------------------------------------
extern "C" void kernel_launch(void* const* d_in, const int* in_sizes, int n_in,
                              void* d_out, int out_size)
{
    const float*    X   = (const float*)d_in[0];
    const unsigned* adj = (const unsigned*)d_in[1];   // bool widened to 32-bit
    const float*    W   = (const float*)d_in[2];
    const float*    a   = (const float*)d_in[3];
    float*          out = (float*)d_out;

    gemm_proj_kernel<<<N_NODES / GM_BM, 256>>>(X, W);
    compute_s_kernel<<<N_NODES / 8, 256>>>(a);
    attn_kernel<<<N_NODES, 256>>>(adj, out);
}

// round 3
// speedup vs baseline: 1.1340x; 1.1340x over previous
#include <cuda_runtime.h>
#include <cstdint>

// Problem constants (fixed by setup_inputs)
#define N_NODES 8192
#define IN_DIM  256
#define OUT_DIM 64
#define SLOPE   0.2f

// Scratch (allocation-free rule: __device__ globals)
__device__ float g_proj[N_NODES * OUT_DIM];   // 2 MB
__device__ float g_si[N_NODES];
__device__ float g_sj[N_NODES];

// ---------------------------------------------------------------------------
// Kernel 1: proj = X[8192,256] @ W[256,64]  +  fused s_i/s_j epilogue.
// BM=64 tile (grid=128), 256 threads, 4x4 micro-tile/thread,
// double-buffered smem with register prefetch to hide DRAM latency.
// ---------------------------------------------------------------------------
#define GM_BM 64
#define GM_BK 32
#define AS_LD 68   // 64 + 4 padding

__global__ __launch_bounds__(256) void gemm_proj_kernel(
    const float* __restrict__ X, const float* __restrict__ W,
    const float* __restrict__ a)
{
    __shared__ float As[2][GM_BK * AS_LD];   // [k][m], padded
    __shared__ float Bs[2][GM_BK][OUT_DIM];  // [k][n]
    __shared__ float a_s[2 * OUT_DIM];

    const int tid = threadIdx.x;
    const int block_row = blockIdx.x * GM_BM;
    const int trow = tid >> 4;   // 0..15 -> rows trow*4 .. +3
    const int tcol = tid & 15;   // 0..15 -> cols tcol*4 .. +3

    if (tid < 128) a_s[tid] = a[tid];

    // indices for the cooperative tile loads (2 float4 each for A and B)
    const int a_r0  = tid >> 3;            // idx = tid       -> row 0..31
    const int a_c4  = tid & 7;
    const int a_r1  = (tid + 256) >> 3;    // row 32..63
    const int b_r0  = tid >> 4;            // 0..15
    const int b_c4  = tid & 15;
    const int b_r1  = (tid + 256) >> 4;    // 16..31

    float4 rA0, rA1, rB0, rB1;

    auto load_tiles = [&](int k0) {
        rA0 = *(const float4*)(X + (size_t)(block_row + a_r0) * IN_DIM + k0 + a_c4 * 4);
        rA1 = *(const float4*)(X + (size_t)(block_row + a_r1) * IN_DIM + k0 + a_c4 * 4);
        rB0 = *(const float4*)(W + (size_t)(k0 + b_r0) * OUT_DIM + b_c4 * 4);
        rB1 = *(const float4*)(W + (size_t)(k0 + b_r1) * OUT_DIM + b_c4 * 4);
    };
    auto store_tiles = [&](int buf) {
        As[buf][(a_c4 * 4 + 0) * AS_LD + a_r0] = rA0.x;
        As[buf][(a_c4 * 4 + 1) * AS_LD + a_r0] = rA0.y;
        As[buf][(a_c4 * 4 + 2) * AS_LD + a_r0] = rA0.z;
        As[buf][(a_c4 * 4 + 3) * AS_LD + a_r0] = rA0.w;
        As[buf][(a_c4 * 4 + 0) * AS_LD + a_r1] = rA1.x;
        As[buf][(a_c4 * 4 + 1) * AS_LD + a_r1] = rA1.y;
        As[buf][(a_c4 * 4 + 2) * AS_LD + a_r1] = rA1.z;
        As[buf][(a_c4 * 4 + 3) * AS_LD + a_r1] = rA1.w;
        *(float4*)&Bs[buf][b_r0][b_c4 * 4] = rB0;
        *(float4*)&Bs[buf][b_r1][b_c4 * 4] = rB1;
    };

    float acc[4][4];
    #pragma unroll
    for (int i = 0; i < 4; i++)
        #pragma unroll
        for (int j = 0; j < 4; j++) acc[i][j] = 0.0f;

    load_tiles(0);
    store_tiles(0);
    __syncthreads();

    const int NT = IN_DIM / GM_BK;   // 8 k-tiles
    for (int t = 0; t < NT; t++) {
        int buf = t & 1;
        if (t + 1 < NT) load_tiles((t + 1) * GM_BK);   // LDG issued before compute

        #pragma unroll
        for (int k = 0; k < GM_BK; k++) {
            float4 av = *(const float4*)&As[buf][k * AS_LD + trow * 4];
            float4 bv = *(const float4*)&Bs[buf][k][tcol * 4];
            float aa[4] = {av.x, av.y, av.z, av.w};
            float bb[4] = {bv.x, bv.y, bv.z, bv.w};
            #pragma unroll
            for (int i = 0; i < 4; i++)
                #pragma unroll
                for (int j = 0; j < 4; j++)
                    acc[i][j] = fmaf(aa[i], bb[j], acc[i][j]);
        }
        if (t + 1 < NT) {
            store_tiles(buf ^ 1);
        }
        __syncthreads();
    }

    // ---- fused epilogue: store proj + compute s_i/s_j ----
    #pragma unroll
    for (int i = 0; i < 4; i++) {
        int row = block_row + trow * 4 + i;
        float4 v = make_float4(acc[i][0], acc[i][1], acc[i][2], acc[i][3]);
        *(float4*)(g_proj + (size_t)row * OUT_DIM + tcol * 4) = v;

        float q0 = acc[i][0] * a_s[tcol * 4 + 0] + acc[i][1] * a_s[tcol * 4 + 1]
                 + acc[i][2] * a_s[tcol * 4 + 2] + acc[i][3] * a_s[tcol * 4 + 3];
        float q1 = acc[i][0] * a_s[64 + tcol * 4 + 0] + acc[i][1] * a_s[64 + tcol * 4 + 1]
                 + acc[i][2] * a_s[64 + tcol * 4 + 2] + acc[i][3] * a_s[64 + tcol * 4 + 3];
        #pragma unroll
        for (int o = 8; o > 0; o >>= 1) {
            q0 += __shfl_down_sync(0xffffffffu, q0, o, 16);
            q1 += __shfl_down_sync(0xffffffffu, q1, o, 16);
        }
        if (tcol == 0) { g_si[row] = q0; g_sj[row] = q1; }
    }
}

// ---------------------------------------------------------------------------
// Kernel 2: per-row sparse softmax-attention (adjacency read as u32 words).
// Deterministic neighbor-list build via count + block exclusive scan.
// ---------------------------------------------------------------------------
#define CAP 1024

__device__ __forceinline__ float leaky(float x) {
    return x > 0.0f ? x : SLOPE * x;
}

__device__ __forceinline__ float block_reduce(float v, float* s8, bool do_max)
{
    int lane = threadIdx.x & 31;
    int warp = threadIdx.x >> 5;
    #pragma unroll
    for (int o = 16; o > 0; o >>= 1) {
        float t = __shfl_xor_sync(0xffffffffu, v, o);
        v = do_max ? fmaxf(v, t) : (v + t);
    }
    __syncthreads();
    if (lane == 0) s8[warp] = v;
    __syncthreads();
    if (threadIdx.x == 0) {
        float r = s8[0];
        #pragma unroll
        for (int w = 1; w < 8; w++)
            r = do_max ? fmaxf(r, s8[w]) : (r + s8[w]);
        s8[0] = r;
    }
    __syncthreads();
    return s8[0];
}

__global__ __launch_bounds__(256) void attn_kernel(
    const unsigned* __restrict__ adj, float* __restrict__ out)
{
    __shared__ int   s_idx[CAP];
    __shared__ float s_w[CAP];
    __shared__ float s_acc[4][OUT_DIM];
    __shared__ float s_red[8];
    __shared__ int   s_wsum[8];
    __shared__ int   s_woff[8];
    __shared__ int   s_cnt;

    const int row = blockIdx.x;
    const int tid = threadIdx.x;
    const int lane = tid & 31;
    const int warp = tid >> 5;

    const unsigned* arow = adj + (size_t)row * N_NODES;   // 8192 words = 32 KB
    const uint4* arow4 = (const uint4*)arow;

    // ---- pass 1: count edges per thread (8 uint4 = 32 elements each) ----
    int c = 0;
    #pragma unroll
    for (int it = 0; it < 8; it++) {
        uint4 v = arow4[tid + it * 256];
        c += (v.x != 0u) + (v.y != 0u) + (v.z != 0u) + (v.w != 0u);
    }

    // ---- block exclusive scan over per-thread counts ----
    int inc = c;
    #pragma unroll
    for (int o = 1; o < 32; o <<= 1) {
        int t = __shfl_up_sync(0xffffffffu, inc, o);
        if (lane >= o) inc += t;
    }
    if (lane == 31) s_wsum[warp] = inc;
    __syncthreads();
    if (tid == 0) {
        int s = 0;
        #pragma unroll
        for (int w = 0; w < 8; w++) { s_woff[w] = s; s += s_wsum[w]; }
        s_cnt = s;
    }
    __syncthreads();
    int off = s_woff[warp] + inc - c;   // exclusive prefix for this thread
    const int cnt = s_cnt;

    // ---- pass 2: ordered write of neighbor indices (row now in L1/L2) ----
    if (cnt <= CAP) {
        #pragma unroll
        for (int it = 0; it < 8; it++) {
            int i4 = tid + it * 256;
            uint4 v = arow4[i4];
            int base = i4 * 4;
            if (v.x) s_idx[off++] = base + 0;
            if (v.y) s_idx[off++] = base + 1;
            if (v.z) s_idx[off++] = base + 2;
            if (v.w) s_idx[off++] = base + 3;
        }
    }
    __syncthreads();

    const float si_r = g_si[row];
    const int   g    = tid >> 6;      // group 0..3
    const int   d    = tid & 63;      // output dim

    if (cnt == 0) {
        // softmax over all-NEG_BIG row is uniform: out = mean(proj)
        float acc = 0.0f;
        for (int j = g; j < N_NODES; j += 4)
            acc += g_proj[(size_t)j * OUT_DIM + d];
        s_acc[g][d] = acc;
        __syncthreads();
        if (g == 0) {
            float tot = s_acc[0][d] + s_acc[1][d] + s_acc[2][d] + s_acc[3][d];
            out[(size_t)row * OUT_DIM + d] = tot * (1.0f / (float)N_NODES);
        }
        return;
    }

    if (cnt <= CAP) {
        // ---- fast path: list-based softmax ----
        float lm = -INFINITY;
        for (int k = tid; k < cnt; k += 256) {
            float e = leaky(si_r + g_sj[s_idx[k]]);
            s_w[k] = e;
            lm = fmaxf(lm, e);
        }
        float m = block_reduce(lm, s_red, true);

        float ls = 0.0f;
        for (int k = tid; k < cnt; k += 256) {
            float w = __expf(s_w[k] - m);
            s_w[k] = w;
            ls += w;
        }
        float denom = block_reduce(ls, s_red, false);

        float acc = 0.0f;
        #pragma unroll 4
        for (int k = g; k < cnt; k += 4)
            acc += s_w[k] * g_proj[(size_t)s_idx[k] * OUT_DIM + d];
        s_acc[g][d] = acc;
        __syncthreads();
        if (g == 0) {
            float tot = s_acc[0][d] + s_acc[1][d] + s_acc[2][d] + s_acc[3][d];
            out[(size_t)row * OUT_DIM + d] = tot / denom;
        }
        return;
    }

    // ---- overflow fallback (cnt > CAP, not expected at p=0.01) ----
    float lm = -INFINITY;
    for (int j = tid; j < N_NODES; j += 256)
        if (arow[j]) lm = fmaxf(lm, leaky(si_r + g_sj[j]));
    float m = block_reduce(lm, s_red, true);

    float ls = 0.0f;
    for (int j = tid; j < N_NODES; j += 256)
        if (arow[j]) ls += __expf(leaky(si_r + g_sj[j]) - m);
    float denom = block_reduce(ls, s_red, false);

    float acc = 0.0f;
    for (int j = g; j < N_NODES; j += 4)
        if (arow[j]) {
            float w = __expf(leaky(si_r + g_sj[j]) - m);
            acc += w * g_proj[(size_t)j * OUT_DIM + d];
        }
    s_acc[g][d] = acc;
    __syncthreads();
    if (g == 0) {
        float tot = s_acc[0][d] + s_acc[1][d] + s_acc[2][d] + s_acc[3][d];
        out[(size_t)row * OUT_DIM + d] = tot / denom;
    }
}

// ---------------------------------------------------------------------------
// Launch
// ---------------------------------------------------------------------------
extern "C" void kernel_launch(void* const* d_in, const int* in_sizes, int n_in,
                              void* d_out, int out_size)
{
    const float*    X   = (const float*)d_in[0];
    const unsigned* adj = (const unsigned*)d_in[1];   // bool widened to 32-bit
    const float*    W   = (const float*)d_in[2];
    const float*    a   = (const float*)d_in[3];
    float*          out = (float*)d_out;

    gemm_proj_kernel<<<N_NODES / GM_BM, 256>>>(X, W, a);
    attn_kernel<<<N_NODES, 256>>>(adj, out);
}